// round 3
// baseline (speedup 1.0000x reference)
#include <cuda_runtime.h>
#include <cuda_bf16.h>

// Problem constants
#define S 8192
#define D 1024
#define E 64
#define CAP 128
#define SHIFT 4096
#define RANK_Y 8
static const long long SEC = (long long)S * E * CAP;   // 67108864

#define GEMM_BLOCKS 128
#define ZERO_BLOCKS 1056

// ---------------- scratch (device globals; no cross-call state) -------------
__device__ int   g_beste[S];
__device__ float g_gmax[S];
__device__ int   g_rank_part[RANK_Y * S];
__device__ int   g_expert_at_p[S];
__device__ int   g_token_at_p[S];
__device__ int   g_choff[S];                 // [128 chunks][64 experts] excl prefix
__device__ float g_me_part[GEMM_BLOCKS * E];
__device__ int   g_cnt_part[GEMM_BLOCKS * E];

// ---------------------------------------------------------------------------
__device__ __forceinline__ void fill_range(float4* o4, long long b, long long e,
                                           int tid) {
    const float4 z = make_float4(0.f, 0.f, 0.f, 0.f);
    long long i = b + tid;
    for (; i + 768 < e; i += 1024) {
        __stcs(o4 + i,       z);
        __stcs(o4 + i + 256, z);
        __stcs(o4 + i + 512, z);
        __stcs(o4 + i + 768, z);
    }
    for (; i < e; i += 256) __stcs(o4 + i, z);
}

// ---------------------------------------------------------------------------
// K1: blocks 0..127  : GEMM (64 tokens x 64 experts) + softmax epilogue,
//                      then fill tail 1/16 of out.
//     blocks 128..   : fill front 15/16 of out.
// ---------------------------------------------------------------------------
__global__ void k1_fused(const float* __restrict__ x,
                         const float* __restrict__ w,
                         float* __restrict__ out, long long out_size) {
    const int tid = threadIdx.x;
    const long long n4 = out_size >> 2;
    const long long F4 = (n4 >> 4) * 15;          // front 15/16 (float4 units)
    float4* o4 = (float4*)out;

    if (blockIdx.x < GEMM_BLOCKS) {
        // ---- GEMM: BM=64, BN=64 (all experts), BK=32, 256 thr, 4x4 tile ----
        __shared__ float sbuf[64 * 65];           // As/Bs alias + logits L[64][65]
        float (*As)[64] = (float(*)[64])sbuf;          // [32][64]
        float (*Bs)[64] = (float(*)[64])(sbuf + 2048); // [32][64]
        __shared__ float smax[64], sinv[64];
        __shared__ int   scnt[E];

        const int m0 = blockIdx.x * 64;
        const int tx = tid & 15;
        const int ty = tid >> 4;
        float acc[4][4];
        #pragma unroll
        for (int i = 0; i < 4; i++)
            #pragma unroll
            for (int j = 0; j < 4; j++) acc[i][j] = 0.0f;

        for (int k0 = 0; k0 < D; k0 += 32) {
            #pragma unroll
            for (int r = 0; r < 8; r++) {
                int l  = tid + r * 256;
                int mm = l & 63;
                int kk = l >> 6;
                As[kk][mm] = x[(long long)(m0 + mm) * D + k0 + kk];
                Bs[kk][mm] = w[(long long)mm * D + k0 + kk];
            }
            __syncthreads();
            #pragma unroll
            for (int kk = 0; kk < 32; kk++) {
                const float4 a = *(const float4*)(&As[kk][ty * 4]);
                const float4 b = *(const float4*)(&Bs[kk][tx * 4]);
                float av[4] = {a.x, a.y, a.z, a.w};
                float bv[4] = {b.x, b.y, b.z, b.w};
                #pragma unroll
                for (int i = 0; i < 4; i++)
                    #pragma unroll
                    for (int j = 0; j < 4; j++)
                        acc[i][j] += av[i] * bv[j];
            }
            __syncthreads();
        }

        // ---- epilogue: logits -> smem, softmax/argmax per token ----
        float* L = sbuf;                           // [64][65] padded
        #pragma unroll
        for (int i = 0; i < 4; i++)
            #pragma unroll
            for (int j = 0; j < 4; j++)
                L[(ty * 4 + i) * 65 + tx * 4 + j] = acc[i][j];
        if (tid < E) scnt[tid] = 0;
        __syncthreads();

        if (tid < 64) {
            const int t = tid;
            float bv = L[t * 65];
            int   bi = 0;
            #pragma unroll 8
            for (int e = 1; e < E; e++) {
                float v = L[t * 65 + e];
                if (v > bv) { bv = v; bi = e; }
            }
            float s = 0.0f;
            #pragma unroll 8
            for (int e = 0; e < E; e++) s += expf(L[t * 65 + e] - bv);
            float inv = 1.0f / s;
            smax[t] = bv;
            sinv[t] = inv;
            g_beste[m0 + t] = bi;
            g_gmax[m0 + t]  = inv;                 // max gate = 1/sum
            atomicAdd(&scnt[bi], 1);
        }
        __syncthreads();
        if (tid < E) {
            const int e = tid;
            float me = 0.0f;
            #pragma unroll 8
            for (int t = 0; t < 64; t++)
                me += expf(L[t * 65 + e] - smax[t]) * sinv[t];
            g_me_part[blockIdx.x * E + e]  = me;
            g_cnt_part[blockIdx.x * E + e] = scnt[e];
        }

        // ---- join fill: tail 1/16 ----
        long long per = (n4 - F4 + GEMM_BLOCKS - 1) / GEMM_BLOCKS;
        long long b = F4 + (long long)blockIdx.x * per;
        long long e = b + per; if (e > n4) e = n4;
        fill_range(o4, b, e, tid);
        if (blockIdx.x == 0 && tid == 0) {
            for (long long i = n4 << 2; i < out_size; i++) out[i] = 0.0f;
        }
    } else {
        // ---- fill front 15/16 ----
        const int zb = blockIdx.x - GEMM_BLOCKS;
        long long per = (F4 + ZERO_BLOCKS - 1) / ZERO_BLOCKS;
        long long b = (long long)zb * per;
        long long e = b + per; if (e > F4) e = F4;
        fill_range(o4, b, e, tid);
    }
}

// ---------------------------------------------------------------------------
// K2: rank by counting (stable argsort of -gmax), partitioned over 8 u-slices
// rank(t) = #{u<t: gmax[u] >= gmax[t]} + #{u>=t: gmax[u] > gmax[t]}
// ---------------------------------------------------------------------------
__global__ void k_rank() {
    __shared__ float sh[1024];
    const int t = blockIdx.x * 256 + threadIdx.x;
    const int ubase = blockIdx.y * 1024;
    for (int i = threadIdx.x; i < 1024; i += 256) sh[i] = g_gmax[ubase + i];
    __syncthreads();
    const float g = g_gmax[t];
    int lo = t - ubase;
    if (lo < 0) lo = 0;
    if (lo > 1024) lo = 1024;
    int cnt = 0;
    for (int j = 0; j < lo; j++)    cnt += (sh[j] >= g);
    for (int j = lo; j < 1024; j++) cnt += (sh[j] >  g);
    g_rank_part[blockIdx.y * S + t] = cnt;
}

// ---------------------------------------------------------------------------
// K3: position (roll), scatter expert/token by position, smem histogram,
//     per-expert exclusive prefix over 128 chunks. Single block, 1024 thr.
// ---------------------------------------------------------------------------
__global__ void k_pospfx() {
    __shared__ int hist[128 * E];                 // 32 KB
    const int tid = threadIdx.x;
    for (int i = tid; i < 128 * E; i += 1024) hist[i] = 0;
    __syncthreads();
    #pragma unroll
    for (int k = 0; k < 8; k++) {
        const int t = tid + k * 1024;
        int r = 0;
        #pragma unroll
        for (int y = 0; y < RANK_Y; y++) r += g_rank_part[y * S + t];
        const int p = (r + SHIFT) & (S - 1);
        const int e = g_beste[t];
        g_expert_at_p[p] = e;
        g_token_at_p[p]  = t;
        atomicAdd(&hist[(p >> 6) * E + e], 1);
    }
    __syncthreads();
    if (tid < E) {
        int run = 0;
        #pragma unroll 1
        for (int b = 0; b < 128; b++) {
            g_choff[b * E + tid] = run;
            run += hist[b * E + tid];
        }
    }
}

// ---------------------------------------------------------------------------
// K4: per-chunk within-chunk rank + sparse scatter of combine/dispatch
// ---------------------------------------------------------------------------
__global__ void k_scatter(float* __restrict__ out) {
    __shared__ int se[64];
    const int i = threadIdx.x;
    const int p = blockIdx.x * 64 + i;
    const int e = g_expert_at_p[p];
    const int t = g_token_at_p[p];
    se[i] = e;
    __syncthreads();
    int c = 0;
    for (int j = 0; j < i; j++) c += (se[j] == e);
    const int loc = g_choff[blockIdx.x * E + e] + c;
    if (loc < CAP) {
        long long base = 1LL + ((long long)t * E + e) * CAP + loc;
        float gv = g_gmax[t];
        out[base]       = gv;     // combine_weights
        out[base + SEC] = 1.0f;   // dispatch_mask
    }
}

// ---------------------------------------------------------------------------
// K5: reduce partials -> l_aux, exp_counts, unrouted_token_rate
// ---------------------------------------------------------------------------
__global__ void k_finalize(float* __restrict__ out) {
    __shared__ float red[E];
    __shared__ int   sc[E];
    const int e = threadIdx.x;
    float me = 0.0f;
    int   c  = 0;
    #pragma unroll 8
    for (int b = 0; b < GEMM_BLOCKS; b++) {
        me += g_me_part[b * E + e];
        c  += g_cnt_part[b * E + e];
    }
    const float inv = 1.0f / (float)S;
    red[e] = (me * inv) * ((float)c * inv);
    sc[e]  = c;
    out[1LL + 2LL * SEC + e] = (float)c;
    __syncthreads();
    if (e == 0) {
        float sum = 0.0f;
        int dropped = 0;
        for (int k = 0; k < E; k++) {
            sum += red[k];
            int d = sc[k] - CAP;
            if (d > 0) dropped += d;
        }
        out[0] = sum * (float)E * 0.01f;
        out[1LL + 2LL * SEC + E] = (float)dropped * inv;
    }
}

// ---------------------------------------------------------------------------
extern "C" void kernel_launch(void* const* d_in, const int* in_sizes, int n_in,
                              void* d_out, int out_size) {
    const float* x = (const float*)d_in[0];   // [S, D]
    const float* w = (const float*)d_in[1];   // [E, D]
    float* out = (float*)d_out;
    long long osz = (long long)out_size;

    k1_fused<<<GEMM_BLOCKS + ZERO_BLOCKS, 256>>>(x, w, out, osz);
    k_rank<<<dim3(S / 256, RANK_Y), 256>>>();
    k_pospfx<<<1, 1024>>>();
    k_scatter<<<S / 64, 64>>>(out);
    k_finalize<<<1, E>>>(out);
}

// round 4
// speedup vs baseline: 1.0784x; 1.0784x over previous
#include <cuda_runtime.h>
#include <cuda_bf16.h>

// Problem constants
#define S 8192
#define D 1024
#define E 64
#define CAP 128
#define SHIFT 4096
#define RANK_Y 8
static const long long SEC = (long long)S * E * CAP;   // 67108864

#define GEMM_BLOCKS 128
#define ZERO_BLOCKS 1024

// ---------------- scratch (device globals; no cross-call state) -------------
__device__ int   g_beste[S];
__device__ float g_gmax[S];
__device__ int   g_rank_part[RANK_Y * S];
__device__ int   g_expert_at_p[S];
__device__ int   g_token_at_p[S];
__device__ int   g_choff[S];                 // [128 chunks][64 experts] excl prefix
__device__ float g_me_part[GEMM_BLOCKS * E];
__device__ int   g_cnt_part[GEMM_BLOCKS * E];

// ---------------------------------------------------------------------------
// K1: blocks 0..127 : GEMM (64 tokens x 64 experts) + softmax epilogue
//     blocks 128..  : grid-stride zero-fill of the whole output (R2 style)
// ---------------------------------------------------------------------------
__global__ void k1_fused(const float* __restrict__ x,
                         const float* __restrict__ w,
                         float* __restrict__ out, long long out_size) {
    const int tid = threadIdx.x;

    if (blockIdx.x < GEMM_BLOCKS) {
        // ---- GEMM: BM=64, BN=64 (all experts), BK=32, 256 thr, 4x4 tile ----
        __shared__ float sbuf[64 * 65];           // As/Bs alias + logits L[64][65]
        float (*As)[64] = (float(*)[64])sbuf;          // [32][64]
        float (*Bs)[64] = (float(*)[64])(sbuf + 2048); // [32][64]
        __shared__ float smax[64], sinv[64];
        __shared__ int   scnt[E];

        const int m0 = blockIdx.x * 64;
        const int tx = tid & 15;
        const int ty = tid >> 4;
        float acc[4][4];
        #pragma unroll
        for (int i = 0; i < 4; i++)
            #pragma unroll
            for (int j = 0; j < 4; j++) acc[i][j] = 0.0f;

        for (int k0 = 0; k0 < D; k0 += 32) {
            #pragma unroll
            for (int r = 0; r < 8; r++) {
                int l  = tid + r * 256;
                int mm = l & 63;
                int kk = l >> 6;
                As[kk][mm] = x[(long long)(m0 + mm) * D + k0 + kk];
                Bs[kk][mm] = w[(long long)mm * D + k0 + kk];
            }
            __syncthreads();
            #pragma unroll
            for (int kk = 0; kk < 32; kk++) {
                const float4 a = *(const float4*)(&As[kk][ty * 4]);
                const float4 b = *(const float4*)(&Bs[kk][tx * 4]);
                float av[4] = {a.x, a.y, a.z, a.w};
                float bv[4] = {b.x, b.y, b.z, b.w};
                #pragma unroll
                for (int i = 0; i < 4; i++)
                    #pragma unroll
                    for (int j = 0; j < 4; j++)
                        acc[i][j] += av[i] * bv[j];
            }
            __syncthreads();
        }

        // ---- epilogue: logits -> smem, softmax/argmax per token ----
        float* L = sbuf;                           // [64][65] padded
        #pragma unroll
        for (int i = 0; i < 4; i++)
            #pragma unroll
            for (int j = 0; j < 4; j++)
                L[(ty * 4 + i) * 65 + tx * 4 + j] = acc[i][j];
        if (tid < E) scnt[tid] = 0;
        __syncthreads();

        if (tid < 64) {
            const int t = tid;
            float bv = L[t * 65];
            int   bi = 0;
            #pragma unroll 8
            for (int e = 1; e < E; e++) {
                float v = L[t * 65 + e];
                if (v > bv) { bv = v; bi = e; }
            }
            float s = 0.0f;
            #pragma unroll 8
            for (int e = 0; e < E; e++) s += expf(L[t * 65 + e] - bv);
            float inv = 1.0f / s;
            smax[t] = bv;
            sinv[t] = inv;
            g_beste[m0 + t] = bi;
            g_gmax[m0 + t]  = inv;                 // max gate = 1/sum
            atomicAdd(&scnt[bi], 1);
        }
        __syncthreads();
        if (tid < E) {
            const int e = tid;
            float me = 0.0f;
            #pragma unroll 8
            for (int t = 0; t < 64; t++)
                me += expf(L[t * 65 + e] - smax[t]) * sinv[t];
            g_me_part[blockIdx.x * E + e]  = me;
            g_cnt_part[blockIdx.x * E + e] = scnt[e];
        }
    } else {
        // ---- zero-fill the whole output buffer (poisoned to 0xAA) ----
        long long n4 = out_size >> 2;
        float4* o4 = (float4*)out;
        const float4 z = make_float4(0.f, 0.f, 0.f, 0.f);
        long long idx    = (long long)(blockIdx.x - GEMM_BLOCKS) * blockDim.x + tid;
        long long stride = (long long)ZERO_BLOCKS * blockDim.x;
        for (; idx < n4; idx += stride) o4[idx] = z;
        if (blockIdx.x == GEMM_BLOCKS) {
            for (long long i = (n4 << 2) + tid; i < out_size; i += blockDim.x)
                out[i] = 0.0f;
        }
    }
}

// ---------------------------------------------------------------------------
// K2: rank by counting (stable argsort of -gmax), partitioned over 8 u-slices
// rank(t) = #{u<t: gmax[u] >= gmax[t]} + #{u>=t: gmax[u] > gmax[t]}
// ---------------------------------------------------------------------------
__global__ void k_rank() {
    __shared__ float sh[1024];
    const int t = blockIdx.x * 256 + threadIdx.x;
    const int ubase = blockIdx.y * 1024;
    for (int i = threadIdx.x; i < 1024; i += 256) sh[i] = g_gmax[ubase + i];
    __syncthreads();
    const float g = g_gmax[t];
    int lo = t - ubase;
    if (lo < 0) lo = 0;
    if (lo > 1024) lo = 1024;
    int cnt = 0;
    for (int j = 0; j < lo; j++)    cnt += (sh[j] >= g);
    for (int j = lo; j < 1024; j++) cnt += (sh[j] >  g);
    g_rank_part[blockIdx.y * S + t] = cnt;
}

// ---------------------------------------------------------------------------
// K3: position (roll), scatter expert/token by position, smem histogram,
//     per-expert exclusive prefix over 128 chunks. Single block, 1024 thr.
// ---------------------------------------------------------------------------
__global__ void k_pospfx() {
    __shared__ int hist[128 * E];                 // 32 KB
    const int tid = threadIdx.x;
    for (int i = tid; i < 128 * E; i += 1024) hist[i] = 0;
    __syncthreads();
    #pragma unroll
    for (int k = 0; k < 8; k++) {
        const int t = tid + k * 1024;
        int r = 0;
        #pragma unroll
        for (int y = 0; y < RANK_Y; y++) r += g_rank_part[y * S + t];
        const int p = (r + SHIFT) & (S - 1);
        const int e = g_beste[t];
        g_expert_at_p[p] = e;
        g_token_at_p[p]  = t;
        atomicAdd(&hist[(p >> 6) * E + e], 1);
    }
    __syncthreads();
    if (tid < E) {
        int run = 0;
        #pragma unroll 1
        for (int b = 0; b < 128; b++) {
            g_choff[b * E + tid] = run;
            run += hist[b * E + tid];
        }
    }
}

// ---------------------------------------------------------------------------
// K4: blocks 0..127: per-chunk rank + sparse scatter. block 128: finalize.
// ---------------------------------------------------------------------------
__global__ void k_scatterfin(float* __restrict__ out) {
    if (blockIdx.x < 128) {
        __shared__ int se[64];
        const int i = threadIdx.x;
        const int p = blockIdx.x * 64 + i;
        const int e = g_expert_at_p[p];
        const int t = g_token_at_p[p];
        se[i] = e;
        __syncthreads();
        int c = 0;
        for (int j = 0; j < i; j++) c += (se[j] == e);
        const int loc = g_choff[blockIdx.x * E + e] + c;
        if (loc < CAP) {
            long long base = 1LL + ((long long)t * E + e) * CAP + loc;
            out[base]       = g_gmax[t];  // combine_weights
            out[base + SEC] = 1.0f;       // dispatch_mask
        }
    } else {
        // finalize: l_aux, exp_counts, unrouted_token_rate
        __shared__ float red[E];
        __shared__ int   sc[E];
        const int e = threadIdx.x;
        float me = 0.0f;
        int   c  = 0;
        #pragma unroll 8
        for (int b = 0; b < GEMM_BLOCKS; b++) {
            me += g_me_part[b * E + e];
            c  += g_cnt_part[b * E + e];
        }
        const float inv = 1.0f / (float)S;
        red[e] = (me * inv) * ((float)c * inv);
        sc[e]  = c;
        out[1LL + 2LL * SEC + e] = (float)c;
        __syncthreads();
        if (e == 0) {
            float sum = 0.0f;
            int dropped = 0;
            for (int k = 0; k < E; k++) {
                sum += red[k];
                int d = sc[k] - CAP;
                if (d > 0) dropped += d;
            }
            out[0] = sum * (float)E * 0.01f;
            out[1LL + 2LL * SEC + E] = (float)dropped * inv;
        }
    }
}

// ---------------------------------------------------------------------------
extern "C" void kernel_launch(void* const* d_in, const int* in_sizes, int n_in,
                              void* d_out, int out_size) {
    const float* x = (const float*)d_in[0];   // [S, D]
    const float* w = (const float*)d_in[1];   // [E, D]
    float* out = (float*)d_out;
    long long osz = (long long)out_size;

    k1_fused<<<GEMM_BLOCKS + ZERO_BLOCKS, 256>>>(x, w, out, osz);
    k_rank<<<dim3(S / 256, RANK_Y), 256>>>();
    k_pospfx<<<1, 1024>>>();
    k_scatterfin<<<129, 64>>>(out);
}